// round 7
// baseline (speedup 1.0000x reference)
#include <cuda_runtime.h>
#include <cstdint>

#define BATCH   131072
#define NHEAD   40
#define DH      60
#define DO      20
#define DI      20
#define HPP     8           // heads per phase
#define NPHASE  5
#define BK20    2621440u    // BATCH * 20

// JAX partitionable threefry random_bits(32):
//   (bits1, bits2) = threefry2x32(key=(0,42), counter=(0, i));  bits = bits1 ^ bits2
// keep ⟺ MSB(bits) == 0  (uniform<0.5 test on the mantissa-stuffed float).
__device__ __forceinline__ uint32_t tf_bits(uint32_t ctr) {
    const uint32_t ks1 = 42u;
    const uint32_t ks2 = 0x1BD11BDAu ^ 42u;   // ks0 ^ ks1 ^ C, ks0 = 0
    uint32_t x0 = 0u;          // 0 + ks0
    uint32_t x1 = ctr + ks1;
#define TF_R4(a, b, c, d)                                          \
    x0 += x1; x1 = __funnelshift_l(x1, x1, a); x1 ^= x0;           \
    x0 += x1; x1 = __funnelshift_l(x1, x1, b); x1 ^= x0;           \
    x0 += x1; x1 = __funnelshift_l(x1, x1, c); x1 ^= x0;           \
    x0 += x1; x1 = __funnelshift_l(x1, x1, d); x1 ^= x0;
    TF_R4(13, 15, 26, 6);   x0 += ks1; x1 += ks2 + 1u;
    TF_R4(17, 29, 16, 24);  x0 += ks2; x1 += 2u;          // + ks0 + 2
    TF_R4(13, 15, 26, 6);   /* +ks0 */ x1 += ks1 + 3u;
    TF_R4(17, 29, 16, 24);  x0 += ks1; x1 += ks2 + 4u;
    TF_R4(13, 15, 26, 6);   x0 += ks2; x1 += 5u;          // + ks0 + 5
#undef TF_R4
    return x0 ^ x1;            // bits1 ^ bits2
}

__global__ __launch_bounds__(256)
void Net_69655779606932_kernel(const float* __restrict__ x,
                               const float* __restrict__ W1,
                               const float* __restrict__ b1,
                               const float* __restrict__ Wh,
                               const float* __restrict__ bh,
                               float* __restrict__ out)
{
    __shared__ __align__(16) float sW1[DI][DH];          // transposed: [d][j]
    __shared__ float sb1[DH];
    __shared__ __align__(16) float sWh[HPP][DH][DO];     // [local_head][hd][o]
    __shared__ float sbh[HPP][DO];

    const int tid = threadIdx.x;
    const int b   = blockIdx.x * 256 + tid;

    // ---- load trunk weights (transposed) ----
    for (int i = tid; i < DH * DI; i += 256) {
        int j = i / DI, d = i % DI;                      // W1 is [60][20]: (j, d)
        sW1[d][j] = W1[i];
    }
    if (tid < DH) sb1[tid] = b1[tid];
    __syncthreads();

    // ---- trunk: h = relu(W1 @ x + b1) ----
    float h[DH];
#pragma unroll
    for (int j = 0; j < DH; j++) h[j] = sb1[j];

    const float4* xv = reinterpret_cast<const float4*>(x + (size_t)b * DI);
#pragma unroll
    for (int q = 0; q < 5; q++) {
        float4 t = xv[q];
        float xd[4] = {t.x, t.y, t.z, t.w};
#pragma unroll
        for (int u = 0; u < 4; u++) {
            int d = 4 * q + u;
            const float4* w = reinterpret_cast<const float4*>(&sW1[d][0]);
#pragma unroll
            for (int r = 0; r < 15; r++) {
                float4 wv = w[r];
                h[4 * r + 0] = fmaf(xd[u], wv.x, h[4 * r + 0]);
                h[4 * r + 1] = fmaf(xd[u], wv.y, h[4 * r + 1]);
                h[4 * r + 2] = fmaf(xd[u], wv.z, h[4 * r + 2]);
                h[4 * r + 3] = fmaf(xd[u], wv.w, h[4 * r + 3]);
            }
        }
    }
#pragma unroll
    for (int j = 0; j < DH; j++) h[j] = fmaxf(h[j], 0.0f);

    // ---- 40 heads in 5 phases of 8 ----
    for (int p = 0; p < NPHASE; p++) {
        __syncthreads();
        for (int idx = tid; idx < HPP * DH * DO; idx += 256) {
            int lh  = idx / (DH * DO);
            int rem = idx % (DH * DO);                   // = o*60 + hd in source
            int o   = rem / DH;
            int hd  = rem % DH;
            sWh[lh][hd][o] = Wh[(p * HPP + lh) * (DH * DO) + rem];
        }
        for (int idx = tid; idx < HPP * DO; idx += 256) {
            sbh[idx / DO][idx % DO] = bh[p * HPP * DO + idx];
        }
        __syncthreads();

#pragma unroll 1
        for (int lh = 0; lh < HPP; lh++) {
            const int k = p * HPP + lh;
            float a[DO];
#pragma unroll
            for (int o = 0; o < DO; o++) a[o] = sbh[lh][o];

#pragma unroll
            for (int hd = 0; hd < DH; hd++) {
                float hv = h[hd];
                const float4* w = reinterpret_cast<const float4*>(&sWh[lh][hd][0]);
#pragma unroll
                for (int q = 0; q < 5; q++) {
                    float4 wv = w[q];
                    a[4 * q + 0] = fmaf(hv, wv.x, a[4 * q + 0]);
                    a[4 * q + 1] = fmaf(hv, wv.y, a[4 * q + 1]);
                    a[4 * q + 2] = fmaf(hv, wv.z, a[4 * q + 2]);
                    a[4 * q + 3] = fmaf(hv, wv.w, a[4 * q + 3]);
                }
            }

            // ---- dropout mask: partitionable threefry, XOR lane-fold ----
            const uint32_t base = (uint32_t)k * BK20 + (uint32_t)b * (uint32_t)DO;
            uint32_t keepmask = 0;
#pragma unroll 4
            for (int o = 0; o < DO; o++) {
                uint32_t r = tf_bits(base + (uint32_t)o);
                keepmask |= ((~r) >> 31) << o;           // keep ⟺ MSB==0
            }

            float* op = out + (size_t)k * BK20 + (size_t)b * DO;
#pragma unroll
            for (int q = 0; q < 5; q++) {
                float v[4];
#pragma unroll
                for (int u = 0; u < 4; u++) {
                    int o = 4 * q + u;
                    uint32_t fbits = ((keepmask >> o) & 1u) << 30;   // 2.0f or 0.0f
                    v[u] = fmaxf(a[o], 0.0f) * __uint_as_float(fbits);
                }
                reinterpret_cast<float4*>(op)[q] = make_float4(v[0], v[1], v[2], v[3]);
            }
        }
    }
}

extern "C" void kernel_launch(void* const* d_in, const int* in_sizes, int n_in,
                              void* d_out, int out_size) {
    const float* x  = (const float*)d_in[0];
    const float* W1 = (const float*)d_in[1];
    const float* b1 = (const float*)d_in[2];
    const float* Wh = (const float*)d_in[3];
    const float* bh = (const float*)d_in[4];
    Net_69655779606932_kernel<<<BATCH / 256, 256>>>(x, W1, b1, Wh, bh, (float*)d_out);
}

// round 10
// speedup vs baseline: 1.1573x; 1.1573x over previous
#include <cuda_runtime.h>
#include <cstdint>

#define BATCH   131072
#define BK20    2621440u    // BATCH * 20

// JAX partitionable threefry random_bits(32):
//   (b1, b2) = threefry2x32(key=(0,42), ctr=(0,i));  bits = b1 ^ b2
// keep ⟺ MSB(bits) == 0.   (validated R7: rel_err 9.7e-8)
__device__ __forceinline__ uint32_t tf_bits(uint32_t ctr) {
    const uint32_t ks1 = 42u;
    const uint32_t ks2 = 0x1BD11BDAu ^ 42u;
    uint32_t x0 = 0u;
    uint32_t x1 = ctr + ks1;
#define TF_R4(a, b, c, d)                                          \
    x0 += x1; x1 = __funnelshift_l(x1, x1, a); x1 ^= x0;           \
    x0 += x1; x1 = __funnelshift_l(x1, x1, b); x1 ^= x0;           \
    x0 += x1; x1 = __funnelshift_l(x1, x1, c); x1 ^= x0;           \
    x0 += x1; x1 = __funnelshift_l(x1, x1, d); x1 ^= x0;
    TF_R4(13, 15, 26, 6);   x0 += ks1; x1 += ks2 + 1u;
    TF_R4(17, 29, 16, 24);  x0 += ks2; x1 += 2u;
    TF_R4(13, 15, 26, 6);   /* ks0 */  x1 += ks1 + 3u;
    TF_R4(17, 29, 16, 24);  x0 += ks1; x1 += ks2 + 4u;
    TF_R4(13, 15, 26, 6);   x0 += ks2; x1 += 5u;
#undef TF_R4
    return x0 ^ x1;
}

// 2 threads per batch element: lane pair (tid, tid^1).
// parity p: hd-half [p*30, p*30+30), output-half [p*10, p*10+10).
__global__ __launch_bounds__(256, 3)
void Net_69655779606932_kernel(const float* __restrict__ x,
                               const float* __restrict__ W1,
                               const float* __restrict__ b1,
                               const float* __restrict__ Wh,
                               const float* __restrict__ bh,
                               float* __restrict__ out)
{
    __shared__ __align__(16) float sW1[20][64];      // [d][j], halves at col 0 / 32
    __shared__ __align__(16) float sb1[64];          // halves at 0 / 32
    __shared__ __align__(16) float sWh[8][60][20];   // [local_head][hd][o]
    __shared__ __align__(16) float sbh[8][20];

    const int tid = threadIdx.x;
    const int p   = tid & 1;
    const int e   = blockIdx.x * 128 + (tid >> 1);

    // ---- stage trunk weights, column-split-padded for aligned half reads ----
    for (int i = tid; i < 1200; i += 256) {
        int j = i / 20, d = i % 20;                  // W1 is [60][20]: (j, d)
        sW1[d][j + (j >= 30 ? 2 : 0)] = W1[i];
    }
    if (tid < 60) sb1[tid + (tid >= 30 ? 2 : 0)] = b1[tid];
    __syncthreads();

    // ---- trunk half: hh[j] = relu(b1 + sum_d x_d * W1[j,d]), j in my 30 ----
    float xr[20];
    {
        const float4* xv = reinterpret_cast<const float4*>(x + (size_t)e * 20);
#pragma unroll
        for (int q = 0; q < 5; q++) {
            float4 t = xv[q];
            xr[4 * q] = t.x; xr[4 * q + 1] = t.y; xr[4 * q + 2] = t.z; xr[4 * q + 3] = t.w;
        }
    }
    float hh[30];
    {
        const float* bp = &sb1[p * 32];
#pragma unroll
        for (int q = 0; q < 7; q++) {
            float4 t = reinterpret_cast<const float4*>(bp)[q];
            hh[4 * q] = t.x; hh[4 * q + 1] = t.y; hh[4 * q + 2] = t.z; hh[4 * q + 3] = t.w;
        }
        float2 t2 = *reinterpret_cast<const float2*>(bp + 28);
        hh[28] = t2.x; hh[29] = t2.y;
    }
#pragma unroll
    for (int d = 0; d < 20; d++) {
        float xd = xr[d];
        const float* wr = &sW1[d][p * 32];
#pragma unroll
        for (int q = 0; q < 7; q++) {
            float4 w = reinterpret_cast<const float4*>(wr)[q];
            hh[4 * q + 0] = fmaf(xd, w.x, hh[4 * q + 0]);
            hh[4 * q + 1] = fmaf(xd, w.y, hh[4 * q + 1]);
            hh[4 * q + 2] = fmaf(xd, w.z, hh[4 * q + 2]);
            hh[4 * q + 3] = fmaf(xd, w.w, hh[4 * q + 3]);
        }
        float2 w2 = *reinterpret_cast<const float2*>(wr + 28);
        hh[28] = fmaf(xd, w2.x, hh[28]);
        hh[29] = fmaf(xd, w2.y, hh[29]);
    }
#pragma unroll
    for (int j = 0; j < 30; j++) hh[j] = fmaxf(hh[j], 0.0f);

    // ---- 40 heads in 5 phases of 8 ----
    for (int ph = 0; ph < 5; ph++) {
        __syncthreads();
        for (int i = tid; i < 8 * 1200; i += 256) {
            int lh = i / 1200, rem = i % 1200;       // rem = o*60 + hd
            int o  = rem / 60, hd = rem % 60;
            sWh[lh][hd][o] = Wh[(ph * 8 + lh) * 1200 + rem];
        }
        for (int i = tid; i < 160; i += 256)
            sbh[i / 20][i % 20] = bh[ph * 160 + i];
        __syncthreads();

#pragma unroll 1
        for (int lh = 0; lh < 8; lh++) {
            const int k = ph * 8 + lh;

            // packed partial accumulators: acc2[q] = (o=2q, o=2q+1)
            uint64_t acc2[10];
#pragma unroll
            for (int q = 0; q < 10; q++) acc2[q] = 0ull;

#pragma unroll
            for (int hd = 0; hd < 30; hd++) {
                uint64_t hv2;
                asm("mov.b64 %0, {%1, %1};" : "=l"(hv2) : "r"(__float_as_uint(hh[hd])));
                const ulonglong2* wr =
                    reinterpret_cast<const ulonglong2*>(&sWh[lh][p * 30 + hd][0]);
#pragma unroll
                for (int q = 0; q < 5; q++) {
                    ulonglong2 w = wr[q];
                    asm("fma.rn.f32x2 %0, %1, %2, %0;" : "+l"(acc2[2 * q])     : "l"(hv2), "l"(w.x));
                    asm("fma.rn.f32x2 %0, %1, %2, %0;" : "+l"(acc2[2 * q + 1]) : "l"(hv2), "l"(w.y));
                }
            }

            // cross-lane reduction: partner holds the other hd-half
#pragma unroll
            for (int q = 0; q < 10; q++) {
                uint64_t other = __shfl_xor_sync(0xFFFFFFFFu, acc2[q], 1);
                asm("add.rn.f32x2 %0, %0, %1;" : "+l"(acc2[q]) : "l"(other));
            }

            const uint32_t cbase = (uint32_t)k * BK20 + (uint32_t)e * 20u + (uint32_t)(p * 10);
            float* op = out + (size_t)k * BK20 + (size_t)e * 20 + p * 10;
            const float* bpp = &sbh[lh][p * 10];

#pragma unroll
            for (int j = 0; j < 5; j++) {
                uint64_t own = p ? acc2[j + 5] : acc2[j];
                uint64_t b2  = *reinterpret_cast<const uint64_t*>(bpp + 2 * j);
                asm("add.rn.f32x2 %0, %0, %1;" : "+l"(own) : "l"(b2));
                uint32_t lo, hi;
                asm("mov.b64 {%0, %1}, %2;" : "=r"(lo), "=r"(hi) : "l"(own));
                uint32_t r0 = tf_bits(cbase + 2u * j);
                uint32_t r1 = tf_bits(cbase + 2u * j + 1u);
                uint32_t f0 = ((~r0) & 0x80000000u) >> 1;    // 0x40000000 = 2.0f or 0
                uint32_t f1 = ((~r1) & 0x80000000u) >> 1;
                float v0 = fmaxf(__uint_as_float(lo), 0.0f) * __uint_as_float(f0);
                float v1 = fmaxf(__uint_as_float(hi), 0.0f) * __uint_as_float(f1);
                *reinterpret_cast<float2*>(op + 2 * j) = make_float2(v0, v1);
            }
        }
    }
}

extern "C" void kernel_launch(void* const* d_in, const int* in_sizes, int n_in,
                              void* d_out, int out_size) {
    const float* x  = (const float*)d_in[0];
    const float* W1 = (const float*)d_in[1];
    const float* b1 = (const float*)d_in[2];
    const float* Wh = (const float*)d_in[3];
    const float* bh = (const float*)d_in[4];
    // 2 threads per element: 262144 threads, 256/block -> 1024 blocks
    Net_69655779606932_kernel<<<(BATCH * 2) / 256, 256>>>(x, W1, b1, Wh, bh, (float*)d_out);
}